// round 12
// baseline (speedup 1.0000x reference)
#include <cuda_runtime.h>
#include <cuda_fp16.h>
#include <math.h>
#include <stdint.h>

#define BB 2048
#define SS 200
#define HALF_S 100
#define DD 128
#define HH 64
#define MASK_SCALE 1e10f
#define NT 256
#define NW (NT / 32)
#define NSTRIP_H 7                   // ceil(100/16); strip 6 has 4 valid rows

#define ASTRIDE 272                  // bytes per A row (136 fp16) = 17*16
#define BSTRIDE 144                  // bytes per B row (72 fp16)  = 9*16

// ---- main-kernel smem layout (split CTA: 112 A rows) ----
#define A_OFF      0                         // 112*272 = 30464
#define B_OFF      30464                     // 18432 -> 48896
#define SM_MASK    48896                     // 128 f -> 49408
#define SM_CO      49408                     // 64 float2 -> 49920
#define SM_SCR     49920                     // 8*128 f -> 54016
#define SM_REDM    54016                     // 8 f -> 54048
#define SM_REDS    54048                     // 8 f -> 54080
#define SMEM_BYTES 54080                     // 52.8 KB -> 3 CTAs/SM (reg-capped)

typedef unsigned long long u64;

__device__ __half g_Bh[DD * 72];     // (W1+W2) fp16, [k][c] padded to 72
__device__ float g_Wb[DD * HH];      // W3 - W2
__device__ float g_c[BB * HH];       // tgt @ Wb + W_bias
// split-softmax partials
__device__ float g_P[2 * BB * DD];   // per-half pooled numerator (scaled by e^m ref)
__device__ float g_m[2 * BB];        // per-half max
__device__ float g_s[2 * BB];        // per-half exp-sum

__device__ __forceinline__ uint32_t smem_u32(const void* p) {
    return (uint32_t)__cvta_generic_to_shared(p);
}
__device__ __forceinline__ void cpa16(void* s, const void* g) {
    asm volatile("cp.async.cg.shared.global [%0], [%1], 16;" :: "r"(smem_u32(s)), "l"(g));
}
#define CP_COMMIT() asm volatile("cp.async.commit_group;")
#define CP_WAIT0()  asm volatile("cp.async.wait_group 0;")

__device__ __forceinline__ void ldsm4(uint32_t* r, uint32_t addr) {
    asm volatile("ldmatrix.sync.aligned.m8n8.x4.shared.b16 {%0,%1,%2,%3}, [%4];"
                 : "=r"(r[0]), "=r"(r[1]), "=r"(r[2]), "=r"(r[3]) : "r"(addr));
}
__device__ __forceinline__ void ldsm4t(uint32_t* r, uint32_t addr) {
    asm volatile("ldmatrix.sync.aligned.m8n8.x4.trans.shared.b16 {%0,%1,%2,%3}, [%4];"
                 : "=r"(r[0]), "=r"(r[1]), "=r"(r[2]), "=r"(r[3]) : "r"(addr));
}
__device__ __forceinline__ void mma16816(float* c, const uint32_t* a,
                                         uint32_t b0, uint32_t b1) {
    asm volatile(
        "mma.sync.aligned.m16n8k16.row.col.f32.f16.f16.f32 "
        "{%0,%1,%2,%3}, {%4,%5,%6,%7}, {%8,%9}, {%0,%1,%2,%3};"
        : "+f"(c[0]), "+f"(c[1]), "+f"(c[2]), "+f"(c[3])
        : "r"(a[0]), "r"(a[1]), "r"(a[2]), "r"(a[3]), "r"(b0), "r"(b1));
}

__global__ void fold_w_kernel(const float* __restrict__ W) {
    int idx = blockIdx.x * blockDim.x + threadIdx.x;
    if (idx < DD * HH) {
        int k = idx >> 6, c = idx & 63;
        float w1 = W[k * HH + c];
        float w2 = W[(DD + k) * HH + c];
        float w3 = W[(2 * DD + k) * HH + c];
        g_Wb[k * HH + c] = w3 - w2;
        g_Bh[k * 72 + c] = __float2half_rn(w1 + w2);
    }
}

__global__ void cvec_kernel(const float* __restrict__ target,
                            const float* __restrict__ W_bias) {
    __shared__ float tgt[DD];
    int b = blockIdx.x;
    for (int i = threadIdx.x; i < DD; i += blockDim.x)
        tgt[i] = target[(size_t)b * DD + i];
    __syncthreads();
    int h = threadIdx.x;
    if (h < HH) {
        float acc = 0.f;
#pragma unroll 8
        for (int d = 0; d < DD; d++)
            acc = fmaf(tgt[d], g_Wb[d * HH + h], acc);
        g_c[b * HH + h] = acc + W_bias[h];
    }
}

// ---- main kernel: one CTA per (batch, half) ----
__global__ __launch_bounds__(NT, 3)
void ta_main_kernel(const float* __restrict__ his,
                    const float* __restrict__ mask,
                    const float* __restrict__ O,
                    const float* __restrict__ O_bias) {
    extern __shared__ __align__(16) char sm[];
    float*  mask_s = (float*)(sm + SM_MASK);
    float2* cO_s   = (float2*)(sm + SM_CO);
    float*  scr    = (float*)(sm + SM_SCR);
    float*  redm   = (float*)(sm + SM_REDM);
    float*  reds   = (float*)(sm + SM_REDS);

    const int bid = blockIdx.x;
    const int b = bid >> 1;
    const int srow0 = (bid & 1) * HALF_S;      // global row offset of this half
    const int tid = threadIdx.x;
    const int wid = tid >> 5;
    const int lane = tid & 31;
    const uint32_t smem_base = smem_u32(sm);

    // ---- Phase 0: B cp.async; mask + cO; own-strip A LDG ----
    for (int i = tid; i < 18432 / 16; i += NT)
        cpa16(sm + B_OFF + i * 16, (const char*)g_Bh + i * 16);
    CP_COMMIT();

    const float ob = O_bias[0];
    if (tid < HALF_S) mask_s[tid] = mask[(size_t)b * SS + srow0 + tid];
    if (tid < HH) cO_s[tid] = make_float2(g_c[b * HH + tid], O[tid]);

    const int nrows = (wid < 6) ? 16 : (wid == 6 ? 4 : 0);
    {
        const int k0 = 4 * lane;
        const int base = wid * 16;             // local row of strip start
        const float* hb = his + ((size_t)b * SS + srow0 + base) * DD + k0;
#pragma unroll 1
        for (int g0 = 0; g0 < nrows; g0 += 8) {
            float4 v[8];
#pragma unroll
            for (int j = 0; j < 8; j++)
                if (g0 + j < nrows) v[j] = *(const float4*)(hb + (size_t)(g0 + j) * DD);
#pragma unroll
            for (int j = 0; j < 8; j++)
                if (g0 + j < nrows) {
                    int s = base + g0 + j;
                    __half2 p01 = __floats2half2_rn(v[j].x, v[j].y);
                    __half2 p23 = __floats2half2_rn(v[j].z, v[j].w);
                    u64 hp = ((u64)*(uint32_t*)&p23 << 32) | *(uint32_t*)&p01;
                    *(u64*)(sm + A_OFF + s * ASTRIDE + k0 * 2) = hp;
                }
        }
    }

    CP_WAIT0();
    __syncthreads();     // B + mask + cO visible; own A rows warp-local

    // ---- Phase 1: single-strip GEMM + fused softmax/pool per warp ----
    if (wid < NSTRIP_H) {
        const int g = lane >> 3;
        const int r = lane & 7;
        const int arow_l = r + (g & 1) * 8;
        const int acol_l = (g >> 1) * 16;
        const int brow_l = r + (g & 1) * 8;
        const uint32_t bH = smem_base + B_OFF + brow_l * BSTRIDE + (g >> 1) * 16;
        const uint32_t Ab = smem_base + A_OFF + (wid * 16 + arow_l) * ASTRIDE + acol_l;

        float c[8][4];
#pragma unroll
        for (int nt = 0; nt < 8; nt++)
#pragma unroll
            for (int q = 0; q < 4; q++) c[nt][q] = 0.f;

#pragma unroll
        for (int kk = 0; kk < 8; kk++) {
            uint32_t a[4];
            ldsm4(a, Ab + kk * 32);            // strip 6 rows 100..111: garbage rows, discarded
            const uint32_t koff = kk * 16 * BSTRIDE;
#pragma unroll
            for (int np2 = 0; np2 < 4; np2++) {
                uint32_t bf[4];
                ldsm4t(bf, bH + koff + np2 * 32);
                mma16816(c[2 * np2],     a, bf[0], bf[1]);
                mma16816(c[2 * np2 + 1], a, bf[2], bf[3]);
            }
        }

        const int qr = lane >> 2;
        const int cbase = 2 * (lane & 3);
        const int sl0 = wid * 16 + qr;         // local rows this lane's quad covers
        const int sl1 = sl0 + 8;
        const bool ok0 = (sl0 < HALF_S) && (qr < nrows);
        const bool ok1 = (sl1 < HALF_S) && (qr + 8 < nrows);

        float v0 = 0.f, v1 = 0.f;
#pragma unroll
        for (int nt = 0; nt < 8; nt++) {
            int col0 = nt * 8 + cbase;
            float2 co0 = cO_s[col0];
            float2 co1 = cO_s[col0 + 1];
            v0 = fmaf(fmaxf(c[nt][0] + co0.x, 0.f), co0.y, v0);
            v0 = fmaf(fmaxf(c[nt][1] + co1.x, 0.f), co1.y, v0);
            v1 = fmaf(fmaxf(c[nt][2] + co0.x, 0.f), co0.y, v1);
            v1 = fmaf(fmaxf(c[nt][3] + co1.x, 0.f), co1.y, v1);
        }
        v0 += __shfl_xor_sync(0xffffffffu, v0, 1);
        v0 += __shfl_xor_sync(0xffffffffu, v0, 2);
        v1 += __shfl_xor_sync(0xffffffffu, v1, 1);
        v1 += __shfl_xor_sync(0xffffffffu, v1, 2);

        v0 = ok0 ? (v0 + ob - mask_s[sl0] * MASK_SCALE) : -INFINITY;
        v1 = ok1 ? (v1 + ob - mask_s[sl1] * MASK_SCALE) : -INFINITY;

        float m = fmaxf(v0, v1);
#pragma unroll
        for (int off = 16; off > 0; off >>= 1)
            m = fmaxf(m, __shfl_xor_sync(0xffffffffu, m, off));

        float e0 = ok0 ? __expf(v0 - m) : 0.f;
        float e1 = ok1 ? __expf(v1 - m) : 0.f;

        float sp = ((lane & 3) == 0) ? (e0 + e1) : 0.f;
#pragma unroll
        for (int off = 16; off > 0; off >>= 1)
            sp += __shfl_xor_sync(0xffffffffu, sp, off);

        if (lane == 0) { redm[wid] = m; reds[wid] = sp; }

        // warp-local pooling of own strip rows; lane owns d = 4*lane..4*lane+3
        float a0 = 0.f, a1 = 0.f, a2 = 0.f, a3 = 0.f;
        const int n0 = (nrows < 8) ? nrows : 8;      // valid rows in low half
        const int n1 = nrows - n0;                    // valid rows in high half
#pragma unroll
        for (int rr = 0; rr < 8; rr++) {
            if (rr < n0) {
                float er = __shfl_sync(0xffffffffu, e0, 4 * rr);
                uint2 hv = *(uint2*)(sm + A_OFF + (wid * 16 + rr) * ASTRIDE + lane * 8);
                float2 f01 = __half22float2(*(__half2*)&hv.x);
                float2 f23 = __half22float2(*(__half2*)&hv.y);
                a0 = fmaf(er, f01.x, a0); a1 = fmaf(er, f01.y, a1);
                a2 = fmaf(er, f23.x, a2); a3 = fmaf(er, f23.y, a3);
            }
            if (rr < n1) {
                float er = __shfl_sync(0xffffffffu, e1, 4 * rr);
                uint2 hv = *(uint2*)(sm + A_OFF + (wid * 16 + 8 + rr) * ASTRIDE + lane * 8);
                float2 f01 = __half22float2(*(__half2*)&hv.x);
                float2 f23 = __half22float2(*(__half2*)&hv.y);
                a0 = fmaf(er, f01.x, a0); a1 = fmaf(er, f01.y, a1);
                a2 = fmaf(er, f23.x, a2); a3 = fmaf(er, f23.y, a3);
            }
        }
        *(float4*)(scr + wid * 128 + lane * 4) = make_float4(a0, a1, a2, a3);
    } else {
        if (lane == 0) { redm[wid] = -INFINITY; reds[wid] = 0.f; }
        *(float4*)(scr + wid * 128 + lane * 4) = make_float4(0.f, 0.f, 0.f, 0.f);
    }
    __syncthreads();

    // ---- Phase 2: CTA-level merge -> global partials ----
    if (tid < DD) {
        float M = redm[0];
#pragma unroll
        for (int q = 1; q < NSTRIP_H; q++) M = fmaxf(M, redm[q]);
        float T = 0.f, acc = 0.f;
#pragma unroll
        for (int q = 0; q < NSTRIP_H; q++) {
            float f = __expf(redm[q] - M);
            T = fmaf(reds[q], f, T);
            acc = fmaf(scr[q * 128 + tid], f, acc);
        }
        g_P[(size_t)bid * DD + tid] = acc;
        if (tid == 0) { g_m[bid] = M; g_s[bid] = T; }
    }
}

// ---- merge kernel: combine the two halves of each batch ----
__global__ __launch_bounds__(128, 16)
void merge_kernel(float* __restrict__ out) {
    const int b = blockIdx.x;
    const int d = threadIdx.x;
    const float m0 = g_m[2 * b], m1 = g_m[2 * b + 1];
    const float M = fmaxf(m0, m1);
    const float f0 = __expf(m0 - M), f1 = __expf(m1 - M);
    const float T = g_s[2 * b] * f0 + g_s[2 * b + 1] * f1;
    const float p = g_P[(size_t)(2 * b) * DD + d] * f0
                  + g_P[(size_t)(2 * b + 1) * DD + d] * f1;
    out[(size_t)b * DD + d] = p / T;
}

extern "C" void kernel_launch(void* const* d_in, const int* in_sizes, int n_in,
                              void* d_out, int out_size) {
    const float* his    = (const float*)d_in[0];
    const float* target = (const float*)d_in[1];
    const float* mask   = (const float*)d_in[2];
    const float* W      = (const float*)d_in[3];
    const float* W_bias = (const float*)d_in[4];
    const float* O      = (const float*)d_in[5];
    const float* O_bias = (const float*)d_in[6];
    float* out = (float*)d_out;

    cudaFuncSetAttribute(ta_main_kernel,
                         cudaFuncAttributeMaxDynamicSharedMemorySize, SMEM_BYTES);

    fold_w_kernel<<<(DD * HH + 255) / 256, 256>>>(W);
    cvec_kernel<<<BB, 128>>>(target, W_bias);
    ta_main_kernel<<<2 * BB, NT, SMEM_BYTES>>>(his, mask, O, O_bias);
    merge_kernel<<<BB, 128>>>(out);
}